// round 3
// baseline (speedup 1.0000x reference)
#include <cuda_runtime.h>
#include <math.h>

// ---------------- problem constants ----------------
namespace {
constexpr int B_   = 8;
constexpr int IMG_ = 128;
constexpr int D_   = 128;
constexpr int H_   = 4;
constexpr int HD_  = 32;
constexpr int L_   = 2;
constexpr int NC_  = 256;   // 16x16 coarse tokens
constexpr int NF_  = 1024;  // 32x32 fine tokens
constexpr int N_   = 1280;  // NC+NF
constexpr int OUT_ = 32;
constexpr float SCALE_ = 0.17677669529663687f; // 32^-0.5
}

// ---------------- scratch (static device globals; no allocations) ----------------
__device__ float g_fine  [B_*NF_*D_];
__device__ float g_tokens[B_*N_*D_];
__device__ float g_y     [B_*N_*D_];
__device__ float g_qkv   [B_*N_*3*D_];
__device__ float g_att   [B_*N_*D_];
__device__ float g_h1    [B_*N_*2*D_];
__device__ float g_e     [B_*NF_];
__device__ int   g_mask  [B_*NF_];
__device__ int   g_order [B_*NF_];
__device__ int   g_ntrue [B_];
__device__ float g_c     [B_*NC_];
__device__ float g_fmap  [B_*NF_];
__device__ float g_fused [B_*2*OUT_*OUT_];
__device__ float g_hb    [B_*2*OUT_*OUT_];

// ---------------- patch embeds ----------------
__global__ void k_coarse(const float* __restrict__ x, const float* __restrict__ Wpc,
                         const float* __restrict__ bpc, const float* __restrict__ te) {
    __shared__ float sp[64];
    int blk = blockIdx.x;
    int b = blk >> 8, tok = blk & 255;
    int i = tok >> 4, j = tok & 15;
    int t = threadIdx.x;
    if (t < 64) {
        int pr = t >> 3, pc = t & 7;
        sp[t] = x[(b*IMG_ + i*8 + pr)*IMG_ + j*8 + pc];
    }
    __syncthreads();
    float acc = 0.f;
    #pragma unroll
    for (int p = 0; p < 64; p++) acc += sp[p] * Wpc[p*D_ + t];
    g_tokens[((size_t)b*N_ + tok)*D_ + t] = acc + bpc[t] + te[t];
}

__global__ void k_fine(const float* __restrict__ x, const float* __restrict__ Wpf,
                       const float* __restrict__ bpf) {
    __shared__ float sp[16];
    int blk = blockIdx.x;
    int b = blk >> 10, tok = blk & 1023;
    int i = tok >> 5, j = tok & 31;
    int t = threadIdx.x;
    if (t < 16) {
        int pr = t >> 2, pc = t & 3;
        sp[t] = x[(b*IMG_ + i*4 + pr)*IMG_ + j*4 + pc];
    }
    __syncthreads();
    float acc = 0.f;
    #pragma unroll
    for (int p = 0; p < 16; p++) acc += sp[p] * Wpf[p*D_ + t];
    g_fine[((size_t)b*NF_ + tok)*D_ + t] = acc + bpf[t];
}

// ---------------- edge map: sobel -> 4x4 avgpool ----------------
__device__ __forceinline__ float xat(const float* x, int b, int y, int c) {
    if ((unsigned)y >= (unsigned)IMG_ || (unsigned)c >= (unsigned)IMG_) return 0.f;
    return x[(b*IMG_ + y)*IMG_ + c];
}

__global__ void k_edge(const float* __restrict__ x) {
    int idx = blockIdx.x*blockDim.x + threadIdx.x;
    if (idx >= B_*NF_) return;
    int b = idx >> 10, cell = idx & 1023;
    int yi = cell >> 5, xi = cell & 31;
    float acc = 0.f;
    for (int dy = 0; dy < 4; dy++)
    for (int dx = 0; dx < 4; dx++) {
        int py = yi*4 + dy, px = xi*4 + dx;
        float a  = xat(x,b,py-1,px-1), bv = xat(x,b,py-1,px), c  = xat(x,b,py-1,px+1);
        float d  = xat(x,b,py  ,px-1),                         e2 = xat(x,b,py  ,px+1);
        float f  = xat(x,b,py+1,px-1), g  = xat(x,b,py+1,px), h2 = xat(x,b,py+1,px+1);
        float gx = -a + c - 2.f*d + 2.f*e2 - f + h2;
        float gy = -a - 2.f*bv - c + f + 2.f*g + h2;
        acc += sqrtf(gx*gx + gy*gy);
    }
    g_e[idx] = acc * (1.f/16.f);
}

__global__ void k_mask() {
    int b = blockIdx.x, t = threadIdx.x;   // 256 threads
    __shared__ float sh[256];
    float s = 0.f;
    for (int i = t; i < NF_; i += 256) s += g_e[b*NF_ + i];
    sh[t] = s; __syncthreads();
    for (int o = 128; o; o >>= 1) { if (t < o) sh[t] += sh[t+o]; __syncthreads(); }
    float mean = sh[0] * (1.f/NF_);
    for (int i = t; i < NF_; i += 256)
        g_mask[b*NF_ + i] = (g_e[b*NF_ + i] > mean) ? 1 : 0;
}

// stable argsort of !mask via prefix sum: edge tokens first, pixel order preserved
__global__ void k_order() {
    int b = blockIdx.x, t = threadIdx.x;   // 1024 threads
    __shared__ int sh[1024];
    int m = g_mask[b*NF_ + t];
    sh[t] = m; __syncthreads();
    for (int o = 1; o < 1024; o <<= 1) {
        int v = (t >= o) ? sh[t-o] : 0;
        __syncthreads();
        sh[t] += v;
        __syncthreads();
    }
    int incl = sh[t];
    int total = sh[1023];
    int pos = m ? (incl - 1) : (total + t - incl);
    g_order[b*NF_ + pos] = t;
    if (t == 0) g_ntrue[b] = total;
}

__global__ void k_assemble(const float* __restrict__ te) {
    int blk = blockIdx.x;
    int b = blk >> 10, pos = blk & 1023;
    int t = threadIdx.x;
    float v = te[D_ + t];
    if (pos < g_ntrue[b])
        v += g_fine[((size_t)b*NF_ + g_order[b*NF_ + pos])*D_ + t];
    g_tokens[((size_t)b*N_ + NC_ + pos)*D_ + t] = v;
}

// ---------------- layernorm (one block per token row, D=128) ----------------
__global__ void k_ln(const float* __restrict__ in, const float* __restrict__ g,
                     const float* __restrict__ bb, float* __restrict__ out) {
    int row = blockIdx.x, t = threadIdx.x;
    float v = in[(size_t)row*D_ + t];
    float s = v, q = v*v;
    #pragma unroll
    for (int o = 16; o; o >>= 1) {
        s += __shfl_xor_sync(~0u, s, o);
        q += __shfl_xor_sync(~0u, q, o);
    }
    __shared__ float ss[4], sq[4];
    int w = t >> 5, lane = t & 31;
    if (lane == 0) { ss[w] = s; sq[w] = q; }
    __syncthreads();
    s = ss[0]+ss[1]+ss[2]+ss[3];
    q = sq[0]+sq[1]+sq[2]+sq[3];
    float mean = s * (1.f/D_);
    float var  = q * (1.f/D_) - mean*mean;
    out[(size_t)row*D_ + t] = (v - mean) * rsqrtf(var + 1e-5f) * g[t] + bb[t];
}

// ---------------- generic SGEMM: C = act(A@W + bias) + res ----------------
// 64x64 block tile, BK=16, 256 threads, 4x4 micro-tile. M,N,K all multiples required.
__global__ __launch_bounds__(256) void sgemm(
    const float* __restrict__ A, const float* __restrict__ Bw,
    const float* __restrict__ bias, const float* __restrict__ res,
    float* __restrict__ C, int M, int Nn, int K, int act)
{
    __shared__ float As[16][64];
    __shared__ float Bs[16][64];
    int t = threadIdx.x;
    int m0 = blockIdx.y*64, n0 = blockIdx.x*64;
    int ty = t >> 4, tx = t & 15;
    float acc[4][4] = {};
    for (int k0 = 0; k0 < K; k0 += 16) {
        {
            int idx = t*4;
            int ar = idx >> 4, ac = idx & 15;
            float4 v = *(const float4*)(A + (size_t)(m0+ar)*K + k0 + ac);
            As[ac  ][ar] = v.x; As[ac+1][ar] = v.y;
            As[ac+2][ar] = v.z; As[ac+3][ar] = v.w;
        }
        {
            int idx = t*4;
            int br = idx >> 6, bc = idx & 63;
            float4 v = *(const float4*)(Bw + (size_t)(k0+br)*Nn + n0 + bc);
            *(float4*)&Bs[br][bc] = v;
        }
        __syncthreads();
        #pragma unroll
        for (int kk = 0; kk < 16; kk++) {
            float a[4], bb4[4];
            #pragma unroll
            for (int i = 0; i < 4; i++) a[i]  = As[kk][ty*4 + i];
            #pragma unroll
            for (int jj = 0; jj < 4; jj++) bb4[jj] = Bs[kk][tx*4 + jj];
            #pragma unroll
            for (int i = 0; i < 4; i++)
                #pragma unroll
                for (int jj = 0; jj < 4; jj++)
                    acc[i][jj] += a[i] * bb4[jj];
        }
        __syncthreads();
    }
    #pragma unroll
    for (int i = 0; i < 4; i++) {
        int m = m0 + ty*4 + i;
        #pragma unroll
        for (int jj = 0; jj < 4; jj++) {
            int n = n0 + tx*4 + jj;
            float v = acc[i][jj];
            if (bias) v += bias[n];
            if (act == 1) v = 0.5f * v * (1.f + erff(v * 0.70710678118654752f));
            if (res)  v += res[(size_t)m*Nn + n];
            C[(size_t)m*Nn + n] = v;
        }
    }
}

// ---------------- attention: online softmax, 32 q / block, 2 q / thread ----------------
__global__ __launch_bounds__(128) void k_attn(const float* __restrict__ qkv,
                                              float* __restrict__ out) {
    __shared__ float Ks[64][36];
    __shared__ float Vs[64][36];
    __shared__ float red[128*34];
    int b = blockIdx.z, h = blockIdx.y, q0 = blockIdx.x*32;
    int t = threadIdx.x;
    int j = t & 7, qp = t >> 3;
    int qa = q0 + qp*2;

    const float* qptr = qkv + ((size_t)b*N_ + qa)*384 + h*32;
    float qra[32], qrb[32];
    #pragma unroll
    for (int d = 0; d < 32; d++) { qra[d] = qptr[d]*SCALE_; qrb[d] = qptr[384+d]*SCALE_; }

    float m0 = -1e30f, s0 = 0.f, m1 = -1e30f, s1 = 0.f;
    float acc0[32], acc1[32];
    #pragma unroll
    for (int d = 0; d < 32; d++) { acc0[d] = 0.f; acc1[d] = 0.f; }

    for (int k0 = 0; k0 < N_; k0 += 64) {
        __syncthreads();
        for (int i = t; i < 512; i += 128) {
            int key = i >> 3, dq = (i & 7) << 2;
            const float* kp = qkv + ((size_t)b*N_ + k0 + key)*384 + 128 + h*32 + dq;
            float4 kv = *(const float4*)kp;
            Ks[key][dq] = kv.x; Ks[key][dq+1] = kv.y; Ks[key][dq+2] = kv.z; Ks[key][dq+3] = kv.w;
            float4 vv = *(const float4*)(kp + 128);
            Vs[key][dq] = vv.x; Vs[key][dq+1] = vv.y; Vs[key][dq+2] = vv.z; Vs[key][dq+3] = vv.w;
        }
        __syncthreads();
        for (int kk = j; kk < 64; kk += 8) {
            float d0 = 0.f, d1 = 0.f;
            #pragma unroll
            for (int d = 0; d < 32; d += 4) {
                float4 kv = *(float4*)&Ks[kk][d];
                d0 += qra[d]*kv.x + qra[d+1]*kv.y + qra[d+2]*kv.z + qra[d+3]*kv.w;
                d1 += qrb[d]*kv.x + qrb[d+1]*kv.y + qrb[d+2]*kv.z + qrb[d+3]*kv.w;
            }
            if (d0 > m0) {
                float f = expf(m0 - d0); s0 *= f;
                #pragma unroll
                for (int d = 0; d < 32; d++) acc0[d] *= f;
                m0 = d0;
            }
            float p0 = expf(d0 - m0); s0 += p0;
            if (d1 > m1) {
                float f = expf(m1 - d1); s1 *= f;
                #pragma unroll
                for (int d = 0; d < 32; d++) acc1[d] *= f;
                m1 = d1;
            }
            float p1 = expf(d1 - m1); s1 += p1;
            #pragma unroll
            for (int d = 0; d < 32; d += 4) {
                float4 vv = *(float4*)&Vs[kk][d];
                acc0[d]   += p0*vv.x; acc0[d+1] += p0*vv.y;
                acc0[d+2] += p0*vv.z; acc0[d+3] += p0*vv.w;
                acc1[d]   += p1*vv.x; acc1[d+1] += p1*vv.y;
                acc1[d+2] += p1*vv.z; acc1[d+3] += p1*vv.w;
            }
        }
    }

    float* r = red + t*34;
    for (int pass = 0; pass < 2; pass++) {
        __syncthreads();
        r[0] = pass ? m1 : m0;
        r[1] = pass ? s1 : s0;
        #pragma unroll
        for (int d = 0; d < 32; d++) r[2+d] = pass ? acc1[d] : acc0[d];
        __syncthreads();
        for (int off = 4; off; off >>= 1) {
            if (j < off) {
                float* o = red + (t+off)*34;
                float mm = fmaxf(r[0], o[0]);
                float f1 = expf(r[0]-mm), f2 = expf(o[0]-mm);
                r[1] = r[1]*f1 + o[1]*f2;
                #pragma unroll
                for (int d = 0; d < 32; d++) r[2+d] = r[2+d]*f1 + o[2+d]*f2;
                r[0] = mm;
            }
            __syncthreads();
        }
        if (j == 0) {
            float inv = 1.f / r[1];
            float* op = out + ((size_t)b*N_ + qa + pass)*D_ + h*32;
            #pragma unroll
            for (int d = 0; d < 32; d++) op[d] = r[2+d]*inv;
        }
    }
}

// ---------------- decoder heads (warp per token) ----------------
__global__ void k_dec(const float* __restrict__ dWc, const float* __restrict__ dbc,
                      const float* __restrict__ dWf, const float* __restrict__ dbf) {
    int gid  = blockIdx.x*blockDim.x + threadIdx.x;
    int warp = gid >> 5;
    int lane = threadIdx.x & 31;
    if (warp >= B_*N_) return;
    int b = warp / N_, i = warp % N_;
    const float* tok = g_tokens + (size_t)warp*D_;
    bool isC = (i < NC_);
    const float* w = isC ? dWc : dWf;
    float a = 0.f;
    for (int d = lane; d < D_; d += 32) a += tok[d]*w[d];
    #pragma unroll
    for (int o = 16; o; o >>= 1) a += __shfl_xor_sync(~0u, a, o);
    if (lane == 0) {
        if (isC) g_c[b*NC_ + i] = a + dbc[0];
        else {
            int pos = i - NC_;
            float v = (pos < g_ntrue[b]) ? (a + dbf[0]) : 0.f;
            g_fmap[b*NF_ + g_order[b*NF_ + pos]] = v;
        }
    }
}

// bilinear (align_corners) upsample coarse 16->32; fine 32->32 is identity
__global__ void k_fuse() {
    int idx = blockIdx.x*blockDim.x + threadIdx.x;
    if (idx >= B_*OUT_*OUT_) return;
    int b = idx >> 10, oy = (idx >> 5) & 31, ox = idx & 31;
    float fy = oy * (15.f/31.f), fx = ox * (15.f/31.f);
    int y0 = (int)floorf(fy), x0 = (int)floorf(fx);
    int y1 = min(y0+1, 15), x1 = min(x0+1, 15);
    float wy = fy - y0, wx = fx - x0;
    const float* c = g_c + b*NC_;
    float cu = c[y0*16+x0]*(1.f-wy)*(1.f-wx) + c[y0*16+x1]*(1.f-wy)*wx
             + c[y1*16+x0]*wy*(1.f-wx)       + c[y1*16+x1]*wy*wx;
    g_fused[((b*2+0)*OUT_ + oy)*OUT_ + ox] = cu;
    g_fused[((b*2+1)*OUT_ + oy)*OUT_ + ox] = g_fmap[b*NF_ + oy*32 + ox];
}

__global__ void k_conv1(const float* __restrict__ w, const float* __restrict__ bias) {
    int idx = blockIdx.x*blockDim.x + threadIdx.x;
    if (idx >= B_*2*OUT_*OUT_) return;
    int ox = idx & 31, oy = (idx >> 5) & 31, co = (idx >> 10) & 1, b = idx >> 11;
    float a = bias[co];
    for (int ci = 0; ci < 2; ci++)
    for (int ky = 0; ky < 3; ky++)
    for (int kx = 0; kx < 3; kx++) {
        int y = oy + ky - 1, x2 = ox + kx - 1;
        if ((unsigned)y < 32u && (unsigned)x2 < 32u)
            a += g_fused[((b*2+ci)*OUT_ + y)*OUT_ + x2] * w[((co*2+ci)*3 + ky)*3 + kx];
    }
    g_hb[((b*2+co)*OUT_ + oy)*OUT_ + ox] = fmaxf(a, 0.f);
}

__global__ void k_conv2(const float* __restrict__ w, const float* __restrict__ bias,
                        float* __restrict__ out) {
    int idx = blockIdx.x*blockDim.x + threadIdx.x;
    if (idx >= B_*OUT_*OUT_) return;
    int ox = idx & 31, oy = (idx >> 5) & 31, b = idx >> 10;
    float a = bias[0];
    for (int ci = 0; ci < 2; ci++)
    for (int ky = 0; ky < 3; ky++)
    for (int kx = 0; kx < 3; kx++) {
        int y = oy + ky - 1, x2 = ox + kx - 1;
        if ((unsigned)y < 32u && (unsigned)x2 < 32u)
            a += g_hb[((b*2+ci)*OUT_ + y)*OUT_ + x2] * w[(ci*3 + ky)*3 + kx];
    }
    out[b*OUT_*OUT_ + oy*OUT_ + ox] = a;
}

// ---------------- host orchestration ----------------
extern "C" void kernel_launch(void* const* d_in, const int* in_sizes, int n_in,
                              void* d_out, int out_size) {
    const float* x    = (const float*)d_in[0];
    const float* Wpc  = (const float*)d_in[1];
    const float* bpc  = (const float*)d_in[2];
    const float* Wpf  = (const float*)d_in[3];
    const float* bpf  = (const float*)d_in[4];
    const float* te   = (const float*)d_in[5];
    const float* ln1g = (const float*)d_in[6];
    const float* ln1b = (const float*)d_in[7];
    const float* Wqkv = (const float*)d_in[8];
    const float* Wo   = (const float*)d_in[9];
    const float* bo   = (const float*)d_in[10];
    const float* ln2g = (const float*)d_in[11];
    const float* ln2b = (const float*)d_in[12];
    const float* W1   = (const float*)d_in[13];
    const float* b1   = (const float*)d_in[14];
    const float* W2   = (const float*)d_in[15];
    const float* b2   = (const float*)d_in[16];
    const float* dWc  = (const float*)d_in[17];
    const float* dbc  = (const float*)d_in[18];
    const float* dWf  = (const float*)d_in[19];
    const float* dbf  = (const float*)d_in[20];
    const float* fW1  = (const float*)d_in[21];
    const float* fb1  = (const float*)d_in[22];
    const float* fW2  = (const float*)d_in[23];
    const float* fb2  = (const float*)d_in[24];
    float* out = (float*)d_out;

    float *p_tokens, *p_y, *p_qkv, *p_att, *p_h1;
    cudaGetSymbolAddress((void**)&p_tokens, g_tokens);
    cudaGetSymbolAddress((void**)&p_y,      g_y);
    cudaGetSymbolAddress((void**)&p_qkv,    g_qkv);
    cudaGetSymbolAddress((void**)&p_att,    g_att);
    cudaGetSymbolAddress((void**)&p_h1,     g_h1);

    const int M = B_ * N_; // 10240

    k_coarse  <<<B_*NC_, 128>>>(x, Wpc, bpc, te);
    k_fine    <<<B_*NF_, 128>>>(x, Wpf, bpf);
    k_edge    <<<(B_*NF_ + 255)/256, 256>>>(x);
    k_mask    <<<B_, 256>>>();
    k_order   <<<B_, 1024>>>();
    k_assemble<<<B_*NF_, 128>>>(te);

    for (int l = 0; l < L_; l++) {
        k_ln<<<M, 128>>>(p_tokens, ln1g + l*D_, ln1b + l*D_, p_y);
        sgemm<<<dim3(384/64, M/64), 256>>>(p_y, Wqkv + (size_t)l*D_*3*D_,
                                           nullptr, nullptr, p_qkv, M, 384, 128, 0);
        k_attn<<<dim3(N_/32, H_, B_), 128>>>(p_qkv, p_att);
        sgemm<<<dim3(128/64, M/64), 256>>>(p_att, Wo + (size_t)l*D_*D_,
                                           bo + l*D_, p_tokens, p_tokens, M, 128, 128, 0);
        k_ln<<<M, 128>>>(p_tokens, ln2g + l*D_, ln2b + l*D_, p_y);
        sgemm<<<dim3(256/64, M/64), 256>>>(p_y, W1 + (size_t)l*D_*2*D_,
                                           b1 + l*2*D_, nullptr, p_h1, M, 256, 128, 1);
        sgemm<<<dim3(128/64, M/64), 256>>>(p_h1, W2 + (size_t)l*2*D_*D_,
                                           b2 + l*D_, p_tokens, p_tokens, M, 128, 256, 0);
    }

    k_dec  <<<(B_*N_*32 + 255)/256, 256>>>(dWc, dbc, dWf, dbf);
    k_fuse <<<(B_*OUT_*OUT_ + 255)/256, 256>>>();
    k_conv1<<<(B_*2*OUT_*OUT_ + 255)/256, 256>>>(fW1, fb1);
    k_conv2<<<(B_*OUT_*OUT_ + 255)/256, 256>>>(fW2, fb2, out);
}